// round 14
// baseline (speedup 1.0000x reference)
#include <cuda_runtime.h>
#include <cuda_fp16.h>
#include <cstdint>

#define Bb 16
#define Tt 16384
#define Ll 10
#define NTILE 512
#define CHUNK 128

// ---------------- scratch (static __device__, no allocs) ----------------
__device__ float  g_h[2][Bb * 64 * Tt];      // fp32 residual stream, double buffered
__device__ __half g_hh[2][Bb * 64 * Tt];     // fp16 shadow of h (GEMM operand)
__device__ __half g_act[Ll][Bb * 64 * Tt];   // per-layer gated activations (fp16)
__device__ __half g_W1[Ll * 128 * 192];      // interleaved (filt/gate) dilated-conv weights
__device__ __half g_W2[Ll * 64 * 64];        // res 1x1 weights (k-major)
__device__ __half g_Wsk[64 * 640];           // skip weights: [o][l*64+i]
__device__ float  g_b1[Ll * 128];            // interleaved fb/gb
__device__ float  g_rb[Ll * 64];
__device__ float  g_bsum[64];                // sum_l sb[l][o]

// ---------------- mma / ldmatrix / cp.async helpers ----------------
__device__ __forceinline__ void mma16816(float c[4], const uint32_t a[4], const uint32_t b[2]) {
    asm volatile(
        "mma.sync.aligned.m16n8k16.row.col.f32.f16.f16.f32 "
        "{%0,%1,%2,%3}, {%4,%5,%6,%7}, {%8,%9}, {%0,%1,%2,%3};\n"
        : "+f"(c[0]), "+f"(c[1]), "+f"(c[2]), "+f"(c[3])
        : "r"(a[0]), "r"(a[1]), "r"(a[2]), "r"(a[3]), "r"(b[0]), "r"(b[1]));
}
__device__ __forceinline__ void ldsm4(uint32_t r[4], uint32_t addr) {
    asm volatile("ldmatrix.sync.aligned.m8n8.x4.shared.b16 {%0,%1,%2,%3}, [%4];"
                 : "=r"(r[0]), "=r"(r[1]), "=r"(r[2]), "=r"(r[3]) : "r"(addr));
}
__device__ __forceinline__ void ldsm4t(uint32_t r[4], uint32_t addr) {
    asm volatile("ldmatrix.sync.aligned.m8n8.x4.trans.shared.b16 {%0,%1,%2,%3}, [%4];"
                 : "=r"(r[0]), "=r"(r[1]), "=r"(r[2]), "=r"(r[3]) : "r"(addr));
}
__device__ __forceinline__ void cpa16(uint32_t dst, const void* src) {
    asm volatile("cp.async.ca.shared.global [%0], [%1], 16;" :: "r"(dst), "l"(src));
}
__device__ __forceinline__ void cpa16z(uint32_t dst, const void* src, int sz) {
    asm volatile("cp.async.ca.shared.global [%0], [%1], 16, %2;" :: "r"(dst), "l"(src), "r"(sz));
}
#define CP_COMMIT asm volatile("cp.async.commit_group;")
#define CP_WAIT0  asm volatile("cp.async.wait_group 0;")
#define BAR_SYNC(id)   asm volatile("bar.sync %0, 512;"   :: "r"(id) : "memory")
#define BAR_ARRIVE(id) asm volatile("bar.arrive %0, 512;" :: "r"(id) : "memory")
#define BAR_HALF(id)   asm volatile("bar.sync %0, 256;"   :: "r"(id) : "memory")

// ---------------- weight prep ----------------
__global__ void prep_kernel(const float* __restrict__ fw, const float* __restrict__ fb,
                            const float* __restrict__ gw, const float* __restrict__ gb,
                            const float* __restrict__ rw, const float* __restrict__ rb,
                            const float* __restrict__ sw, const float* __restrict__ sb) {
    int idx = blockIdx.x * blockDim.x + threadIdx.x;
    if (idx < Ll * 128 * 192) {   // W1 interleaved filt/gate
        int l = idx / (128 * 192);
        int rem = idx - l * 128 * 192;
        int row = rem / 192, r = rem - row * 192;
        int k = r >> 6, i = r & 63;
        int tile = row >> 4, rr = row & 15;
        int o = tile * 8 + (rr & 7);
        int src = ((l * 64 + o) * 64 + i) * 3 + k;
        float v = (rr < 8) ? fw[src] : gw[src];
        g_W1[idx] = __float2half_rn(v);
    }
    if (idx < Ll * 64 * 64) {     // W2 = rw, k-major copy
        g_W2[idx] = __float2half_rn(rw[idx]);
    }
    if (idx < 64 * 640) {         // Wsk[o][l*64+i] = sw[l][o][i]
        int o = idx / 640, kk = idx - o * 640;
        int l = kk >> 6, i = kk & 63;
        g_Wsk[idx] = __float2half_rn(sw[(l * 64 + o) * 64 + i]);
    }
    if (idx < Ll * 128) {         // interleaved conv biases
        int l = idx >> 7, row = idx & 127;
        int tile = row >> 4, rr = row & 15;
        int o = tile * 8 + (rr & 7);
        g_b1[idx] = (rr < 8) ? fb[l * 64 + o] : gb[l * 64 + o];
    }
    if (idx < Ll * 64) g_rb[idx] = rb[idx];
    if (idx < 64) {
        float s = 0.f;
        for (int l = 0; l < Ll; l++) s += sb[l * 64 + idx];
        g_bsum[idx] = s;
    }
}

// ---------------- input 1x1 conv: x[B,T,F=32] -> h0[B,C=64,T] ----------------
__global__ __launch_bounds__(256) void input_conv_kernel(const float* __restrict__ x,
                                                         const float* __restrict__ w,
                                                         const float* __restrict__ bias) {
    __shared__ float sx[128 * 33];
    __shared__ float swt[64 * 32];
    __shared__ float sb[64];
    int tid = threadIdx.x;
    int n0 = blockIdx.x * 128;
    int b = n0 >> 14, t0 = n0 & 16383;

    for (int idx = tid; idx < 128 * 32; idx += 256) {
        int j = idx >> 5, f = idx & 31;
        sx[j * 33 + f] = x[(b * Tt + t0 + j) * 32 + f];
    }
    for (int idx = tid; idx < 2048; idx += 256) swt[idx] = w[idx];
    if (tid < 64) sb[tid] = bias[tid];
    __syncthreads();

    for (int oi = tid; oi < 64 * 128; oi += 256) {
        int c = oi >> 7, j = oi & 127;
        float s = sb[c];
#pragma unroll
        for (int f = 0; f < 32; f++) s = fmaf(swt[c * 32 + f], sx[j * 33 + f], s);
        int ofs = (b * 64 + c) * Tt + t0 + j;
        g_h[0][ofs] = s;
        g_hh[0][ofs] = __float2half_rn(s);
    }
}

// ---------------- per-layer fused kernel: warp-specialized producer/consumer ----------------
// Warps 0-7 (A): gather + GEMM1 + act epilogue -> sAct ring (2 buffers)
// Warps 8-15 (B): GEMM2 + residual epilogue, one chunk behind
// smem halves: W1 [128][200] @0, W2 [64][72] @25600, sAct0 [64][136] @30208,
//              sAct1 @38912, sX0 [192][136] @47616, sX1 @73728 (end 99840h = 199680B)
#define ST_X   136
#define ST_W1  200
#define ST_W2  72
#define ST_ACT 136
#define OFF_W1h   0
#define OFF_W2h   25600
#define OFF_ACT0h 30208
#define OFF_ACT1h 38912
#define OFF_X0h   47616
#define OFF_X1h   73728
#define L_SMEM_BYTES 199680
// named barriers: 1,2 = full[buf], 3,4 = empty[buf], 5 = A-internal, 6 = B-internal

// wide gather (d>=8, offsets mult of 8): 16B cp.async, 3072 ops over 256 threads
__device__ __forceinline__ void gatherA_w16(uint32_t su, __half* smh, int xoff_h,
                                            const __half* __restrict__ hhin,
                                            int b, int tc0, int d, int tid) {
#pragma unroll
    for (int it = 0; it < 12; it++) {
        int idx = tid + it * 256;
        int r = idx >> 4, cc = idx & 15;
        int k = r >> 6, i = r & 63;
        int off = (2 - k) * d;
        int tb = tc0 + cc * 8 - off;
        uint32_t dst = su + (uint32_t)(xoff_h + r * ST_X + cc * 8) * 2;
        const __half* src = hhin + ((b * 64 + i) * Tt + (tb >= 0 ? tb : 0));
        cpa16z(dst, src, (tb >= 0) ? 16 : 0);
    }
}
// small-d panel (d<=4): rows 128..191 = hh[i][tc-8 .. tc+127], 1088 ops
__device__ __forceinline__ void gatherA_panel(uint32_t su, __half* smh, int xoff_h,
                                              const __half* __restrict__ hhin,
                                              int b, int tc0, int tid) {
    for (int idx = tid; idx < 1088; idx += 256) {
        int i = idx / 17, cc = idx - i * 17;
        int tb = tc0 - 8 + cc * 8;
        uint32_t dst = su + (uint32_t)(xoff_h + (128 + i) * ST_X + cc * 8) * 2;
        const __half* src = hhin + ((b * 64 + i) * Tt + (tb >= 0 ? tb : 0));
        cpa16z(dst, src, (tb >= 0) ? 16 : 0);
    }
}
// realign taps 0,1 from panel rows 128..191 into rows 0..127 (256 threads)
__device__ __forceinline__ void realign_taps(__half* smh, int xoff_h, int d, int tid) {
    const uint32_t* base32 = reinterpret_cast<const uint32_t*>(smh + xoff_h);
#pragma unroll
    for (int it = 0; it < 8; it++) {     // 2048 uint4 groups
        int gidx = tid + it * 256;
        int k = gidx >> 10;
        int i = (gidx >> 4) & 63;
        int j0 = (gidx & 15) * 8;
        int ofs = 8 - (2 - k) * d;
        int s = ofs + j0;
        const uint32_t* src = base32 + (128 + i) * (ST_X / 2);
        int a = s >> 1;
        uint32_t o0, o1, o2, o3;
        if (s & 1) {
            uint32_t w0 = src[a], w1 = src[a + 1], w2 = src[a + 2], w3 = src[a + 3], w4 = src[a + 4];
            o0 = __funnelshift_r(w0, w1, 16); o1 = __funnelshift_r(w1, w2, 16);
            o2 = __funnelshift_r(w2, w3, 16); o3 = __funnelshift_r(w3, w4, 16);
        } else {
            o0 = src[a]; o1 = src[a + 1]; o2 = src[a + 2]; o3 = src[a + 3];
        }
        *reinterpret_cast<uint4*>(smh + xoff_h + (k * 64 + i) * ST_X + j0) = make_uint4(o0, o1, o2, o3);
    }
}

__global__ void __launch_bounds__(512, 1) layer_kernel(int l, int d, int bufin) {
    extern __shared__ __half smh[];
    const uint32_t su = (uint32_t)__cvta_generic_to_shared(smh);

    const int tid = threadIdx.x;
    const int lane = tid & 31, wid = tid >> 5;
    const int g = lane >> 2, tig = lane & 3;
    const int l15 = lane & 15;
    const int lc8 = (lane >> 4) << 3;

    const int small = (d <= 4);
    const uint32_t t2ofs = small ? 16u : 0u;

    const int n0 = blockIdx.x * NTILE;
    const int b = n0 >> 14;
    const int t0 = n0 & 16383;

    const float* __restrict__ hin = g_h[bufin];
    float* __restrict__ hout = g_h[bufin ^ 1];
    const __half* __restrict__ hhin = g_hh[bufin];
    __half* __restrict__ hhout = g_hh[bufin ^ 1];
    __half* __restrict__ actout = g_act[l];

    if (wid < 8) {
        // ================= PRODUCER (A): gather + GEMM1 + act =================
        const int atid = tid;                 // 0..255
        const int mgA = wid & 3;              // m-group (spans SMSPs)
        const int ngA = wid >> 2;             // 0/1 -> 64-col halves
        const int wmA = mgA * 32;
        const int wnA = ngA * 64;

        // stage W1 (3072 x 16B over 256 threads) + gather chunk 0
        {
            const __half* W1g = g_W1 + l * 128 * 192;
#pragma unroll
            for (int it = 0; it < 12; it++) {
                int idx = atid + it * 256;
                int r = idx / 24, c = idx - r * 24;
                cpa16(su + (uint32_t)(OFF_W1h + r * ST_W1 + c * 8) * 2, W1g + r * 192 + c * 8);
            }
        }
        if (small) gatherA_panel(su, smh, OFF_X0h, hhin, b, t0, atid);
        else       gatherA_w16(su, smh, OFF_X0h, hhin, b, t0, d, atid);
        CP_COMMIT;

        float bfil[2], bgat[2];
#pragma unroll
        for (int mt = 0; mt < 2; mt++) {
            int tile = mgA * 2 + mt;
            bfil[mt] = g_b1[l * 128 + tile * 16 + g];
            bgat[mt] = g_b1[l * 128 + tile * 16 + 8 + g];
        }

        for (int c = 0; c < 4; c++) {
            const int tc = t0 + c * CHUNK;
            const int xcur = (c & 1) ? OFF_X1h : OFF_X0h;
            CP_WAIT0;
            BAR_HALF(5);
            if (c < 3) {
                int xnext = (c & 1) ? OFF_X0h : OFF_X1h;
                if (small) gatherA_panel(su, smh, xnext, hhin, b, tc + CHUNK, atid);
                else       gatherA_w16(su, smh, xnext, hhin, b, tc + CHUNK, d, atid);
                CP_COMMIT;
            }
            if (small) {
                realign_taps(smh, xcur, d, atid);
                BAR_HALF(5);
            }

            // GEMM1: warp tile 32 rows x 64 cols
            float acc[2][8][4];
#pragma unroll
            for (int mt = 0; mt < 2; mt++)
#pragma unroll
                for (int nt = 0; nt < 8; nt++)
#pragma unroll
                    for (int q = 0; q < 4; q++) acc[mt][nt][q] = 0.f;
            {
                uint32_t aAddr = su + (uint32_t)(OFF_W1h + (wmA + l15) * ST_W1 + lc8) * 2;
                uint32_t bAddr = su + (uint32_t)(xcur + l15 * ST_X + wnA + lc8) * 2;
#pragma unroll
                for (int kb = 0; kb < 12; kb++) {
                    if (kb == 8) bAddr += t2ofs;
                    uint32_t a0[4], a1[4];
                    ldsm4(a0, aAddr);
                    ldsm4(a1, aAddr + 16 * ST_W1 * 2);
                    uint32_t bf[4][4];
#pragma unroll
                    for (int np = 0; np < 4; np++) ldsm4t(bf[np], bAddr + np * 32);
#pragma unroll
                    for (int np = 0; np < 4; np++) {
                        mma16816(acc[0][np * 2],     a0, &bf[np][0]);
                        mma16816(acc[0][np * 2 + 1], a0, &bf[np][2]);
                        mma16816(acc[1][np * 2],     a1, &bf[np][0]);
                        mma16816(acc[1][np * 2 + 1], a1, &bf[np][2]);
                    }
                    aAddr += 32;
                    bAddr += 16 * ST_X * 2;
                }
            }
            // wait consumer done with this sAct buffer (ring depth 2)
            if (c >= 2) BAR_SYNC(3 + (c & 1));
            int sact = (c & 1) ? OFF_ACT1h : OFF_ACT0h;
#pragma unroll
            for (int mt = 0; mt < 2; mt++) {
                int o = (mgA * 2 + mt) * 8 + g;
#pragma unroll
                for (int nt = 0; nt < 8; nt++) {
                    int j0 = wnA + nt * 8 + 2 * tig;
                    float f0 = 1.f - 2.f / (__expf(2.f * (acc[mt][nt][0] + bfil[mt])) + 1.f);
                    float f1 = 1.f - 2.f / (__expf(2.f * (acc[mt][nt][1] + bfil[mt])) + 1.f);
                    float s0 = 1.f / (1.f + __expf(-(acc[mt][nt][2] + bgat[mt])));
                    float s1 = 1.f / (1.f + __expf(-(acc[mt][nt][3] + bgat[mt])));
                    __half2 av = __floats2half2_rn(f0 * s0, f1 * s1);
                    *reinterpret_cast<__half2*>(smh + sact + o * ST_ACT + j0) = av;
                    *reinterpret_cast<__half2*>(&actout[(b * 64 + o) * Tt + tc + j0]) = av;
                }
            }
            BAR_ARRIVE(1 + (c & 1));   // full(buf)
        }
    } else {
        // ================= CONSUMER (B): GEMM2 + residual epilogue =================
        const int btid = tid - 256;           // 0..255
        const int w = wid - 8;
        const int mtB = w & 3;                // m16 tile of 64 rows
        const int ngB = w >> 2;               // 64-col half
        const int wnB = ngB * 64;

        // stage W2 (512 x 16B over 256 threads)
        {
            const __half* W2g = g_W2 + l * 64 * 64;
#pragma unroll
            for (int it = 0; it < 2; it++) {
                int idx = btid + it * 256;
                int r = idx >> 3, c = idx & 7;
                cpa16(su + (uint32_t)(OFF_W2h + r * ST_W2 + c * 8) * 2, W2g + r * 64 + c * 8);
            }
        }
        CP_COMMIT;
        CP_WAIT0;
        BAR_HALF(6);

        const int o_a = mtB * 16 + g;
        const int o_b = mtB * 16 + 8 + g;
        const float brs_a = g_rb[l * 64 + o_a];
        const float brs_b = g_rb[l * 64 + o_b];

        for (int c = 0; c < 4; c++) {
            const int tc = t0 + c * CHUNK;
            // prefetch residual rows for this chunk
            float2 hpa[8], hpb[8];
#pragma unroll
            for (int nt = 0; nt < 8; nt++) {
                int j0 = wnB + nt * 8 + 2 * tig;
                hpa[nt] = *reinterpret_cast<const float2*>(&hin[(b * 64 + o_a) * Tt + tc + j0]);
                hpb[nt] = *reinterpret_cast<const float2*>(&hin[(b * 64 + o_b) * Tt + tc + j0]);
            }
            BAR_SYNC(1 + (c & 1));            // wait full(buf)
            int sact = (c & 1) ? OFF_ACT1h : OFF_ACT0h;

            float acc2[8][4];
#pragma unroll
            for (int nt = 0; nt < 8; nt++)
#pragma unroll
                for (int q = 0; q < 4; q++) acc2[nt][q] = 0.f;
            {
                uint32_t aAddr = su + (uint32_t)(OFF_W2h + (mtB * 16 + l15) * ST_W2 + lc8) * 2;
                uint32_t bAddr = su + (uint32_t)(sact + l15 * ST_ACT + wnB + lc8) * 2;
#pragma unroll
                for (int kb = 0; kb < 4; kb++) {
                    uint32_t a0[4];
                    ldsm4(a0, aAddr);
                    uint32_t bf[4][4];
#pragma unroll
                    for (int np = 0; np < 4; np++) ldsm4t(bf[np], bAddr + np * 32);
#pragma unroll
                    for (int np = 0; np < 4; np++) {
                        mma16816(acc2[np * 2],     a0, &bf[np][0]);
                        mma16816(acc2[np * 2 + 1], a0, &bf[np][2]);
                    }
                    aAddr += 32;
                    bAddr += 16 * ST_ACT * 2;
                }
            }
            BAR_ARRIVE(3 + (c & 1));          // empty(buf): done reading sAct

            // epilogue2: h' = (h + res)*0.7071
#pragma unroll
            for (int nt = 0; nt < 8; nt++) {
                int j0 = wnB + nt * 8 + 2 * tig;
                float2 ya, yb;
                ya.x = (hpa[nt].x + acc2[nt][0] + brs_a) * 0.7071f;
                ya.y = (hpa[nt].y + acc2[nt][1] + brs_a) * 0.7071f;
                yb.x = (hpb[nt].x + acc2[nt][2] + brs_b) * 0.7071f;
                yb.y = (hpb[nt].y + acc2[nt][3] + brs_b) * 0.7071f;
                int basea = (b * 64 + o_a) * Tt + tc + j0;
                int baseb = (b * 64 + o_b) * Tt + tc + j0;
                *reinterpret_cast<float2*>(&hout[basea]) = ya;
                *reinterpret_cast<float2*>(&hout[baseb]) = yb;
                *reinterpret_cast<__half2*>(&hhout[basea]) = __floats2half2_rn(ya.x, ya.y);
                *reinterpret_cast<__half2*>(&hhout[baseb]) = __floats2half2_rn(yb.x, yb.y);
            }
        }
    }
}

// ---------------- fused output: skip GEMM (K=640) + relu + fp32 head (round-12 version) ----------------
#define ST_WSK 648
#define OFFO_A0h 41472
#define OFFO_A1h 50176
#define OFFO_F32 117760
#define O_SMEM_BYTES 169472

__device__ __forceinline__ void stage_act(uint32_t su, int dsth, const __half* __restrict__ a,
                                          int b, int tbase, int tid) {
#pragma unroll
    for (int it = 0; it < 2; it++) {
        int idx = tid + it * 512;           // 1024 = 64 rows x 16 x 16B
        int r = idx >> 4, c = idx & 15;
        cpa16(su + (uint32_t)(dsth + r * ST_X + c * 8) * 2,
              a + (b * 64 + r) * Tt + tbase + c * 8);
    }
}

__global__ void __launch_bounds__(512, 1) output_kernel(const float* __restrict__ ow1,
                                                        const float* __restrict__ ob1,
                                                        const float* __restrict__ ow2,
                                                        const float* __restrict__ ob2,
                                                        float* __restrict__ out) {
    extern __shared__ __half smh[];
    const uint32_t su = (uint32_t)__cvta_generic_to_shared(smh);
    float* sS   = reinterpret_cast<float*>(reinterpret_cast<char*>(smh) + OFFO_F32);
    float* sW1o = sS + 64 * 132;
    float* sw2  = sW1o + 64 * 68;
    float* sb1  = sw2 + 64;

    const int tid = threadIdx.x;
    const int lane = tid & 31, wid = tid >> 5;
    const int g = lane >> 2, tig = lane & 3;
    const int l15 = lane & 15;
    const int lc8 = (lane >> 4) << 3;
    const int wm = (wid & 3) * 16;       // 4 m16 tiles
    const int wn = (wid >> 2) * 32;      // 4 n-groups of 32

    const int n0 = blockIdx.x * 512;
    const int b = n0 >> 14, t0 = n0 & 16383;

    // stage Wsk (64 rows x 80 x 16B chunks) + act (l=0, chunk=0)
#pragma unroll
    for (int it = 0; it < 10; it++) {
        int idx = tid + it * 512;
        int r = idx / 80, c = idx - r * 80;
        cpa16(su + (uint32_t)(r * ST_WSK + c * 8) * 2, g_Wsk + r * 640 + c * 8);
    }
    stage_act(su, OFFO_A0h, g_act[0], b, t0, tid);
    CP_COMMIT;

    for (int idx = tid; idx < 4096; idx += 512) {
        int u = idx >> 6, cch = idx & 63;
        sW1o[cch * 68 + u] = ow1[idx];
    }
    if (tid < 64) { sw2[tid] = ow2[tid]; sb1[tid] = ob1[tid]; }

    for (int c = 0; c < 4; c++) {
        float acc[4][4];
#pragma unroll
        for (int nt = 0; nt < 4; nt++)
#pragma unroll
            for (int q = 0; q < 4; q++) acc[nt][q] = 0.f;

        for (int l = 0; l < Ll; l++) {
            int n = c * Ll + l;
            CP_WAIT0;
            __syncthreads();
            if (n < 4 * Ll - 1) {
                int nn = n + 1, nl = nn % Ll, ncc = nn / Ll;
                stage_act(su, (nn & 1) ? OFFO_A1h : OFFO_A0h, g_act[nl],
                          b, t0 + ncc * 128, tid);
                CP_COMMIT;
            }
            int abuf = (n & 1) ? OFFO_A1h : OFFO_A0h;
#pragma unroll
            for (int kb = 0; kb < 4; kb++) {
                uint32_t a0[4];
                ldsm4(a0, su + (uint32_t)((wm + l15) * ST_WSK + l * 64 + kb * 16 + lc8) * 2);
                uint32_t bf0[4], bf1[4];
                uint32_t bAddr = su + (uint32_t)(abuf + (kb * 16 + l15) * ST_X + wn + lc8) * 2;
                ldsm4t(bf0, bAddr);
                ldsm4t(bf1, bAddr + 32);
                mma16816(acc[0], a0, &bf0[0]);
                mma16816(acc[1], a0, &bf0[2]);
                mma16816(acc[2], a0, &bf1[0]);
                mma16816(acc[3], a0, &bf1[2]);
            }
        }
        {
            int o_a = wm + g, o_b = wm + 8 + g;
            float ba = g_bsum[o_a], bb = g_bsum[o_b];
#pragma unroll
            for (int nt = 0; nt < 4; nt++) {
                int j0 = wn + nt * 8 + 2 * tig;
                sS[o_a * 132 + j0]     = fmaxf(acc[nt][0] + ba, 0.f);
                sS[o_a * 132 + j0 + 1] = fmaxf(acc[nt][1] + ba, 0.f);
                sS[o_b * 132 + j0]     = fmaxf(acc[nt][2] + bb, 0.f);
                sS[o_b * 132 + j0 + 1] = fmaxf(acc[nt][3] + bb, 0.f);
            }
        }
        __syncthreads();
        {
            int tl = tid >> 2, pq = tid & 3;
            float a2[16];
#pragma unroll
            for (int q = 0; q < 16; q++) a2[q] = sb1[4 * q + pq];
#pragma unroll 4
            for (int cch = 0; cch < 64; cch++) {
                float v = sS[cch * 132 + tl];
#pragma unroll
                for (int q = 0; q < 16; q++) a2[q] = fmaf(sW1o[cch * 68 + 4 * q + pq], v, a2[q]);
            }
            float y = 0.f;
#pragma unroll
            for (int q = 0; q < 16; q++) y += sw2[4 * q + pq] * fmaxf(a2[q], 0.f);
            y += __shfl_xor_sync(0xFFFFFFFFu, y, 1);
            y += __shfl_xor_sync(0xFFFFFFFFu, y, 2);
            if (pq == 0) out[b * Tt + t0 + c * 128 + tl] = y + ob2[0];
        }
        __syncthreads();
    }
}

// ---------------- launcher ----------------
extern "C" void kernel_launch(void* const* d_in, const int* in_sizes, int n_in,
                              void* d_out, int out_size) {
    (void)in_sizes; (void)n_in; (void)out_size;
    const float* x    = (const float*)d_in[0];
    const float* w_in = (const float*)d_in[1];
    const float* b_in = (const float*)d_in[2];
    const float* fw   = (const float*)d_in[3];
    const float* fb   = (const float*)d_in[4];
    const float* gw   = (const float*)d_in[5];
    const float* gb   = (const float*)d_in[6];
    const float* rw   = (const float*)d_in[7];
    const float* rb   = (const float*)d_in[8];
    const float* sw   = (const float*)d_in[9];
    const float* sb   = (const float*)d_in[10];
    const float* ow1  = (const float*)d_in[11];
    const float* ob1  = (const float*)d_in[12];
    const float* ow2  = (const float*)d_in[13];
    const float* ob2  = (const float*)d_in[14];
    float* out = (float*)d_out;

    static const int dil[Ll] = {1, 2, 4, 8, 16, 32, 64, 128, 256, 512};

    cudaFuncSetAttribute((const void*)layer_kernel,
                         cudaFuncAttributeMaxDynamicSharedMemorySize, L_SMEM_BYTES);
    cudaFuncSetAttribute((const void*)output_kernel,
                         cudaFuncAttributeMaxDynamicSharedMemorySize, O_SMEM_BYTES);

    prep_kernel<<<960, 256>>>(fw, fb, gw, gb, rw, rb, sw, sb);
    input_conv_kernel<<<(Bb * Tt) / 128, 256>>>(x, w_in, b_in);

    int buf = 0;
    for (int l = 0; l < Ll; l++) {
        layer_kernel<<<(Bb * Tt) / NTILE, 512, L_SMEM_BYTES>>>(l, dil[l], buf);
        buf ^= 1;
    }
    output_kernel<<<(Bb * Tt) / 512, 512, O_SMEM_BYTES>>>(ow1, ob1, ow2, ob2, out);
}

// round 15
// speedup vs baseline: 1.3495x; 1.3495x over previous
#include <cuda_runtime.h>
#include <cuda_fp16.h>
#include <cstdint>

#define Bb 16
#define Tt 16384
#define Ll 10
#define CHUNK 128
#define NCHUNK 2048          // (Bb*Tt)/CHUNK
#define GRIDP 148            // persistent grid

// ---------------- scratch (static __device__, no allocs) ----------------
__device__ float  g_h[2][Bb * 64 * Tt];      // fp32 residual stream, double buffered
__device__ __half g_hh[2][Bb * 64 * Tt];     // fp16 shadow of h (GEMM operand)
__device__ __half g_act[Ll][Bb * 64 * Tt];   // per-layer gated activations (fp16)
__device__ __half g_W1[Ll * 128 * 192];      // interleaved (filt/gate) dilated-conv weights
__device__ __half g_W2[Ll * 64 * 64];        // res 1x1 weights (k-major)
__device__ __half g_Wsk[64 * 640];           // skip weights: [o][l*64+i]
__device__ float  g_b1[Ll * 128];            // interleaved fb/gb
__device__ float  g_rb[Ll * 64];
__device__ float  g_bsum[64];                // sum_l sb[l][o]

// ---------------- mma / ldmatrix / cp.async helpers ----------------
__device__ __forceinline__ void mma16816(float c[4], const uint32_t a[4], const uint32_t b[2]) {
    asm volatile(
        "mma.sync.aligned.m16n8k16.row.col.f32.f16.f16.f32 "
        "{%0,%1,%2,%3}, {%4,%5,%6,%7}, {%8,%9}, {%0,%1,%2,%3};\n"
        : "+f"(c[0]), "+f"(c[1]), "+f"(c[2]), "+f"(c[3])
        : "r"(a[0]), "r"(a[1]), "r"(a[2]), "r"(a[3]), "r"(b[0]), "r"(b[1]));
}
__device__ __forceinline__ void ldsm4(uint32_t r[4], uint32_t addr) {
    asm volatile("ldmatrix.sync.aligned.m8n8.x4.shared.b16 {%0,%1,%2,%3}, [%4];"
                 : "=r"(r[0]), "=r"(r[1]), "=r"(r[2]), "=r"(r[3]) : "r"(addr));
}
__device__ __forceinline__ void ldsm4t(uint32_t r[4], uint32_t addr) {
    asm volatile("ldmatrix.sync.aligned.m8n8.x4.trans.shared.b16 {%0,%1,%2,%3}, [%4];"
                 : "=r"(r[0]), "=r"(r[1]), "=r"(r[2]), "=r"(r[3]) : "r"(addr));
}
__device__ __forceinline__ void cpa16(uint32_t dst, const void* src) {
    asm volatile("cp.async.ca.shared.global [%0], [%1], 16;" :: "r"(dst), "l"(src));
}
__device__ __forceinline__ void cpa16z(uint32_t dst, const void* src, int sz) {
    asm volatile("cp.async.ca.shared.global [%0], [%1], 16, %2;" :: "r"(dst), "l"(src), "r"(sz));
}
#define CP_COMMIT asm volatile("cp.async.commit_group;")
#define CP_WAIT0  asm volatile("cp.async.wait_group 0;")

// ---------------- weight prep ----------------
__global__ void prep_kernel(const float* __restrict__ fw, const float* __restrict__ fb,
                            const float* __restrict__ gw, const float* __restrict__ gb,
                            const float* __restrict__ rw, const float* __restrict__ rb,
                            const float* __restrict__ sw, const float* __restrict__ sb) {
    int idx = blockIdx.x * blockDim.x + threadIdx.x;
    if (idx < Ll * 128 * 192) {   // W1 interleaved filt/gate
        int l = idx / (128 * 192);
        int rem = idx - l * 128 * 192;
        int row = rem / 192, r = rem - row * 192;
        int k = r >> 6, i = r & 63;
        int tile = row >> 4, rr = row & 15;
        int o = tile * 8 + (rr & 7);
        int src = ((l * 64 + o) * 64 + i) * 3 + k;
        float v = (rr < 8) ? fw[src] : gw[src];
        g_W1[idx] = __float2half_rn(v);
    }
    if (idx < Ll * 64 * 64) {     // W2 = rw, k-major copy
        g_W2[idx] = __float2half_rn(rw[idx]);
    }
    if (idx < 64 * 640) {         // Wsk[o][l*64+i] = sw[l][o][i]
        int o = idx / 640, kk = idx - o * 640;
        int l = kk >> 6, i = kk & 63;
        g_Wsk[idx] = __float2half_rn(sw[(l * 64 + o) * 64 + i]);
    }
    if (idx < Ll * 128) {         // interleaved conv biases
        int l = idx >> 7, row = idx & 127;
        int tile = row >> 4, rr = row & 15;
        int o = tile * 8 + (rr & 7);
        g_b1[idx] = (rr < 8) ? fb[l * 64 + o] : gb[l * 64 + o];
    }
    if (idx < Ll * 64) g_rb[idx] = rb[idx];
    if (idx < 64) {
        float s = 0.f;
        for (int l = 0; l < Ll; l++) s += sb[l * 64 + idx];
        g_bsum[idx] = s;
    }
}

// ---------------- input 1x1 conv: x[B,T,F=32] -> h0[B,C=64,T] ----------------
__global__ __launch_bounds__(256) void input_conv_kernel(const float* __restrict__ x,
                                                         const float* __restrict__ w,
                                                         const float* __restrict__ bias) {
    __shared__ float sx[128 * 33];
    __shared__ float swt[64 * 32];
    __shared__ float sb[64];
    int tid = threadIdx.x;
    int n0 = blockIdx.x * 128;
    int b = n0 >> 14, t0 = n0 & 16383;

    for (int idx = tid; idx < 128 * 32; idx += 256) {
        int j = idx >> 5, f = idx & 31;
        sx[j * 33 + f] = x[(b * Tt + t0 + j) * 32 + f];
    }
    for (int idx = tid; idx < 2048; idx += 256) swt[idx] = w[idx];
    if (tid < 64) sb[tid] = bias[tid];
    __syncthreads();

    for (int oi = tid; oi < 64 * 128; oi += 256) {
        int c = oi >> 7, j = oi & 127;
        float s = sb[c];
#pragma unroll
        for (int f = 0; f < 32; f++) s = fmaf(swt[c * 32 + f], sx[j * 33 + f], s);
        int ofs = (b * 64 + c) * Tt + t0 + j;
        g_h[0][ofs] = s;
        g_hh[0][ofs] = __float2half_rn(s);
    }
}

// ---------------- per-layer fused kernel (persistent, pipelined) ----------------
// smem halves: W1 [128][200] @0, W2 [64][72] @25600, sAct [64][136] @30208,
//              sX0 [192][136] @38912, sX1 @65024. Total 91136 halves = 182272 B.
#define ST_X   136
#define ST_W1  200
#define ST_W2  72
#define ST_ACT 136
#define OFF_W1h  0
#define OFF_W2h  25600
#define OFF_ACTh 30208
#define OFF_X0h  38912
#define OFF_X1h  65024
#define L_SMEM_BYTES (91136 * 2)

// wide path (d>=8, offsets multiples of 8): 16B cp.async, all 192 rows
__device__ __forceinline__ void issue_gather_w16(uint32_t su, int xoff_h,
                                                 const __half* __restrict__ hhin,
                                                 int b, int tc0, int d, int tid) {
#pragma unroll
    for (int it = 0; it < 6; it++) {     // 3072 = 192 rows x 16 x 16B
        int idx = tid + it * 512;
        int r = idx >> 4, cc = idx & 15;
        int k = r >> 6, i = r & 63;
        int off = (2 - k) * d;
        int tb = tc0 + cc * 8 - off;
        uint32_t dst = su + (uint32_t)(xoff_h + r * ST_X + cc * 8) * 2;
        const __half* src = hhin + ((b * 64 + i) * Tt + (tb >= 0 ? tb : 0));
        cpa16z(dst, src, (tb >= 0) ? 16 : 0);
    }
}

// small-d panel (d<=4): rows 128..191 = hh[i][tc-8 .. tc+127], 1088 ops
__device__ __forceinline__ void issue_gather_panel(uint32_t su, int xoff_h,
                                                   const __half* __restrict__ hhin,
                                                   int b, int tc0, int tid) {
    for (int idx = tid; idx < 1088; idx += 512) {
        int i = idx / 17, cc = idx - i * 17;
        int tb = tc0 - 8 + cc * 8;
        uint32_t dst = su + (uint32_t)(xoff_h + (128 + i) * ST_X + cc * 8) * 2;
        const __half* src = hhin + ((b * 64 + i) * Tt + (tb >= 0 ? tb : 0));
        cpa16z(dst, src, (tb >= 0) ? 16 : 0);
    }
}

// realign taps 0,1 from panel rows 128..191 into rows 0..127
__device__ __forceinline__ void realign_taps(__half* smh, int xoff_h, int d, int tid) {
    const uint32_t* base32 = reinterpret_cast<const uint32_t*>(smh + xoff_h);
#pragma unroll
    for (int it = 0; it < 4; it++) {     // 2048 uint4 groups
        int gidx = tid + it * 512;
        int k = gidx >> 10;
        int i = (gidx >> 4) & 63;
        int j0 = (gidx & 15) * 8;
        int ofs = 8 - (2 - k) * d;
        int s = ofs + j0;
        const uint32_t* src = base32 + (128 + i) * (ST_X / 2);
        int a = s >> 1;
        uint32_t o0, o1, o2, o3;
        if (s & 1) {
            uint32_t w0 = src[a], w1 = src[a + 1], w2 = src[a + 2], w3 = src[a + 3], w4 = src[a + 4];
            o0 = __funnelshift_r(w0, w1, 16); o1 = __funnelshift_r(w1, w2, 16);
            o2 = __funnelshift_r(w2, w3, 16); o3 = __funnelshift_r(w3, w4, 16);
        } else {
            o0 = src[a]; o1 = src[a + 1]; o2 = src[a + 2]; o3 = src[a + 3];
        }
        *reinterpret_cast<uint4*>(smh + xoff_h + (k * 64 + i) * ST_X + j0) = make_uint4(o0, o1, o2, o3);
    }
}

__device__ __forceinline__ void gather_dispatch(uint32_t su, int xoff_h,
                                                const __half* __restrict__ hhin,
                                                int ci, int d, int small, int tid) {
    int b = ci >> 7;
    int tc0 = (ci & 127) * CHUNK;
    if (small) issue_gather_panel(su, xoff_h, hhin, b, tc0, tid);
    else       issue_gather_w16(su, xoff_h, hhin, b, tc0, d, tid);
}

__global__ void __launch_bounds__(512, 1) layer_kernel(int l, int d, int bufin) {
    extern __shared__ __half smh[];
    const uint32_t su = (uint32_t)__cvta_generic_to_shared(smh);

    const int tid = threadIdx.x;
    const int lane = tid & 31, wid = tid >> 5;
    const int g = lane >> 2, tig = lane & 3;
    const int l15 = lane & 15;
    const int lc8 = (lane >> 4) << 3;
    // GEMM1 map: 4 m-groups x 4 n-groups
    const int wm1 = (wid >> 2) * 32, wn1 = (wid & 3) * 32;
    // GEMM2 map: 2 m-groups x 8 n-groups
    const int wm2 = (wid >> 3) * 32, wn2 = (wid & 7) * 16;

    const int small = (d <= 4);
    const uint32_t t2ofs = small ? 16u : 0u;   // tap-2 panel origin shift (+8 halves)

    const float* __restrict__ hin = g_h[bufin];
    float* __restrict__ hout = g_h[bufin ^ 1];
    const __half* __restrict__ hhin = g_hh[bufin];
    __half* __restrict__ hhout = g_hh[bufin ^ 1];
    __half* __restrict__ actout = g_act[l];

    // ---- prologue: stage W1 (3072 x 16B), W2 (512 x 16B), gather first chunk ----
    {
        const __half* W1g = g_W1 + l * 128 * 192;
#pragma unroll
        for (int it = 0; it < 6; it++) {
            int idx = tid + it * 512;       // 3072 = 128 rows x 24 x 16B
            int r = idx / 24, c = idx - r * 24;
            cpa16(su + (uint32_t)(OFF_W1h + r * ST_W1 + c * 8) * 2, W1g + r * 192 + c * 8);
        }
        const __half* W2g = g_W2 + l * 64 * 64;
        {
            int r = tid >> 3, c = tid & 7;  // 512 = 64 rows x 8 x 16B
            cpa16(su + (uint32_t)(OFF_W2h + r * ST_W2 + c * 8) * 2, W2g + r * 64 + c * 8);
        }
    }
    gather_dispatch(su, OFF_X0h, hhin, blockIdx.x, d, small, tid);
    CP_COMMIT;

    // per-thread biases (chunk-independent)
    float bfil[2], bgat[2], brs[2][2];
#pragma unroll
    for (int mt = 0; mt < 2; mt++) {
        int tile1 = (wid >> 2) * 2 + mt;
        bfil[mt] = g_b1[l * 128 + tile1 * 16 + g];
        bgat[mt] = g_b1[l * 128 + tile1 * 16 + 8 + g];
        int tile2 = (wid >> 3) * 2 + mt;
        brs[mt][0] = g_rb[l * 64 + tile2 * 16 + g];
        brs[mt][1] = g_rb[l * 64 + tile2 * 16 + 8 + g];
    }

    int itc = 0;
    for (int ci = blockIdx.x; ci < NCHUNK; ci += GRIDP, itc++) {
        const int b = ci >> 7;
        const int tc = (ci & 127) * CHUNK;
        const int xcur = (itc & 1) ? OFF_X1h : OFF_X0h;
        CP_WAIT0;
        __syncthreads();
        if (ci + GRIDP < NCHUNK) {
            int xnext = (itc & 1) ? OFF_X0h : OFF_X1h;
            gather_dispatch(su, xnext, hhin, ci + GRIDP, d, small, tid);
            CP_COMMIT;
        }
        if (small) {
            realign_taps(smh, xcur, d, tid);
            __syncthreads();
        }
        // prefetch hin (residual) for this chunk
        float2 hpre[2][2][2];
#pragma unroll
        for (int mt = 0; mt < 2; mt++) {
            int o_a = ((wid >> 3) * 2 + mt) * 16 + g;
#pragma unroll
            for (int nt = 0; nt < 2; nt++) {
                int j0 = wn2 + nt * 8 + 2 * tig;
                hpre[mt][nt][0] = *reinterpret_cast<const float2*>(&hin[(b * 64 + o_a) * Tt + tc + j0]);
                hpre[mt][nt][1] = *reinterpret_cast<const float2*>(&hin[(b * 64 + o_a + 8) * Tt + tc + j0]);
            }
        }

        // ---- GEMM1: [128 x 192] x [192 x 128] ----
        float acc[2][4][4];
#pragma unroll
        for (int mt = 0; mt < 2; mt++)
#pragma unroll
            for (int nt = 0; nt < 4; nt++)
#pragma unroll
                for (int q = 0; q < 4; q++) acc[mt][nt][q] = 0.f;
        {
            uint32_t aAddr = su + (uint32_t)(OFF_W1h + (wm1 + l15) * ST_W1 + lc8) * 2;
            uint32_t bAddr = su + (uint32_t)(xcur + l15 * ST_X + wn1 + lc8) * 2;
#pragma unroll
            for (int kb = 0; kb < 12; kb++) {
                if (kb == 8) bAddr += t2ofs;   // tap-2 rows live at +8 halves for small-d panel
                uint32_t a0[4], a1[4];
                ldsm4(a0, aAddr);
                ldsm4(a1, aAddr + 16 * ST_W1 * 2);
                uint32_t bf0[4], bf1[4];
                ldsm4t(bf0, bAddr);
                ldsm4t(bf1, bAddr + 32);
                mma16816(acc[0][0], a0, &bf0[0]);
                mma16816(acc[0][1], a0, &bf0[2]);
                mma16816(acc[0][2], a0, &bf1[0]);
                mma16816(acc[0][3], a0, &bf1[2]);
                mma16816(acc[1][0], a1, &bf0[0]);
                mma16816(acc[1][1], a1, &bf0[2]);
                mma16816(acc[1][2], a1, &bf1[0]);
                mma16816(acc[1][3], a1, &bf1[2]);
                aAddr += 32;
                bAddr += 16 * ST_X * 2;
            }
        }
        // ---- epilogue1: act = tanh(filt)*sigmoid(gate) -> sAct + global act ----
#pragma unroll
        for (int mt = 0; mt < 2; mt++) {
            int o = ((wid >> 2) * 2 + mt) * 8 + g;
#pragma unroll
            for (int nt = 0; nt < 4; nt++) {
                int j0 = wn1 + nt * 8 + 2 * tig;
                float f0 = 1.f - 2.f / (__expf(2.f * (acc[mt][nt][0] + bfil[mt])) + 1.f);
                float f1 = 1.f - 2.f / (__expf(2.f * (acc[mt][nt][1] + bfil[mt])) + 1.f);
                float s0 = 1.f / (1.f + __expf(-(acc[mt][nt][2] + bgat[mt])));
                float s1 = 1.f / (1.f + __expf(-(acc[mt][nt][3] + bgat[mt])));
                __half2 av = __floats2half2_rn(f0 * s0, f1 * s1);
                *reinterpret_cast<__half2*>(smh + OFF_ACTh + o * ST_ACT + j0) = av;
                *reinterpret_cast<__half2*>(&actout[(b * 64 + o) * Tt + tc + j0]) = av;
            }
        }
        __syncthreads();

        // ---- GEMM2 (res only): [64 x 64] x [64 x 128] ----
        float acc2[2][2][4];
#pragma unroll
        for (int mt = 0; mt < 2; mt++)
#pragma unroll
            for (int nt = 0; nt < 2; nt++)
#pragma unroll
                for (int q = 0; q < 4; q++) acc2[mt][nt][q] = 0.f;
        {
            uint32_t aAddr = su + (uint32_t)(OFF_W2h + (wm2 + l15) * ST_W2 + lc8) * 2;
            uint32_t bAddr = su + (uint32_t)(OFF_ACTh + l15 * ST_ACT + wn2 + lc8) * 2;
#pragma unroll
            for (int kb = 0; kb < 4; kb++) {
                uint32_t a0[4], a1[4];
                ldsm4(a0, aAddr);
                ldsm4(a1, aAddr + 16 * ST_W2 * 2);
                uint32_t bf0[4];
                ldsm4t(bf0, bAddr);
                mma16816(acc2[0][0], a0, &bf0[0]);
                mma16816(acc2[0][1], a0, &bf0[2]);
                mma16816(acc2[1][0], a1, &bf0[0]);
                mma16816(acc2[1][1], a1, &bf0[2]);
                aAddr += 32;
                bAddr += 16 * ST_ACT * 2;
            }
        }
        // ---- epilogue2: h' = (h + res)*0.7071 ----
#pragma unroll
        for (int mt = 0; mt < 2; mt++) {
            int o_a = ((wid >> 3) * 2 + mt) * 16 + g;
#pragma unroll
            for (int nt = 0; nt < 2; nt++) {
                int j0 = wn2 + nt * 8 + 2 * tig;
                float2 ha = hpre[mt][nt][0];
                float2 hb = hpre[mt][nt][1];
                float2 ya, yb;
                ya.x = (ha.x + acc2[mt][nt][0] + brs[mt][0]) * 0.7071f;
                ya.y = (ha.y + acc2[mt][nt][1] + brs[mt][0]) * 0.7071f;
                yb.x = (hb.x + acc2[mt][nt][2] + brs[mt][1]) * 0.7071f;
                yb.y = (hb.y + acc2[mt][nt][3] + brs[mt][1]) * 0.7071f;
                int basea = (b * 64 + o_a) * Tt + tc + j0;
                int baseb = (b * 64 + o_a + 8) * Tt + tc + j0;
                *reinterpret_cast<float2*>(&hout[basea]) = ya;
                *reinterpret_cast<float2*>(&hout[baseb]) = yb;
                *reinterpret_cast<__half2*>(&hhout[basea]) = __floats2half2_rn(ya.x, ya.y);
                *reinterpret_cast<__half2*>(&hhout[baseb]) = __floats2half2_rn(yb.x, yb.y);
            }
        }
    }
}

// ---------------- fused output: persistent skip GEMM (K=640) + relu + fp32 head ----------------
// smem halves: Wsk [64][648] @0, actbuf0 [64][136] @41472, actbuf1 @50176 (end 117760B)
// fp32 @117760: sS [64][132], sW1o [64][68], sw2[64], sb1[64]  (total 169472B)
#define ST_WSK 648
#define OFFO_A0h 41472
#define OFFO_A1h 50176
#define OFFO_F32 117760
#define O_SMEM_BYTES 169472

__device__ __forceinline__ void stage_act(uint32_t su, int dsth, const __half* __restrict__ a,
                                          int ci, int tid) {
    int b = ci >> 7;
    int tbase = (ci & 127) * CHUNK;
#pragma unroll
    for (int it = 0; it < 2; it++) {
        int idx = tid + it * 512;           // 1024 = 64 rows x 16 x 16B
        int r = idx >> 4, c = idx & 15;
        cpa16(su + (uint32_t)(dsth + r * ST_X + c * 8) * 2,
              a + (b * 64 + r) * Tt + tbase + c * 8);
    }
}

__global__ void __launch_bounds__(512, 1) output_kernel(const float* __restrict__ ow1,
                                                        const float* __restrict__ ob1,
                                                        const float* __restrict__ ow2,
                                                        const float* __restrict__ ob2,
                                                        float* __restrict__ out) {
    extern __shared__ __half smh[];
    const uint32_t su = (uint32_t)__cvta_generic_to_shared(smh);
    float* sS   = reinterpret_cast<float*>(reinterpret_cast<char*>(smh) + OFFO_F32);
    float* sW1o = sS + 64 * 132;
    float* sw2  = sW1o + 64 * 68;
    float* sb1  = sw2 + 64;

    const int tid = threadIdx.x;
    const int lane = tid & 31, wid = tid >> 5;
    const int g = lane >> 2, tig = lane & 3;
    const int l15 = lane & 15;
    const int lc8 = (lane >> 4) << 3;
    const int wm = (wid & 3) * 16;       // 4 m16 tiles
    const int wn = (wid >> 2) * 32;      // 4 n-groups of 32

    // stage Wsk (64 rows x 80 x 16B chunks) + act (first chunk, l=0)
#pragma unroll
    for (int it = 0; it < 10; it++) {
        int idx = tid + it * 512;
        int r = idx / 80, c = idx - r * 80;
        cpa16(su + (uint32_t)(r * ST_WSK + c * 8) * 2, g_Wsk + r * 640 + c * 8);
    }
    stage_act(su, OFFO_A0h, g_act[0], blockIdx.x, tid);
    CP_COMMIT;

    // stage fp32 head weights (plain)
    for (int idx = tid; idx < 4096; idx += 512) {
        int u = idx >> 6, cch = idx & 63;
        sW1o[cch * 68 + u] = ow1[idx];
    }
    if (tid < 64) { sw2[tid] = ow2[tid]; sb1[tid] = ob1[tid]; }

    int nstage = 0;
    for (int ci = blockIdx.x; ci < NCHUNK; ci += GRIDP) {
        const int b = ci >> 7;
        const int t0 = (ci & 127) * CHUNK;
        float acc[4][4];
#pragma unroll
        for (int nt = 0; nt < 4; nt++)
#pragma unroll
            for (int q = 0; q < 4; q++) acc[nt][q] = 0.f;

        for (int l = 0; l < Ll; l++) {
            CP_WAIT0;
            __syncthreads();
            // prefetch next stage: (ci, l+1) or (ci+GRIDP, 0)
            if (l < Ll - 1) {
                stage_act(su, ((nstage + 1) & 1) ? OFFO_A1h : OFFO_A0h, g_act[l + 1], ci, tid);
                CP_COMMIT;
            } else if (ci + GRIDP < NCHUNK) {
                stage_act(su, ((nstage + 1) & 1) ? OFFO_A1h : OFFO_A0h, g_act[0], ci + GRIDP, tid);
                CP_COMMIT;
            }
            int abuf = (nstage & 1) ? OFFO_A1h : OFFO_A0h;
#pragma unroll
            for (int kb = 0; kb < 4; kb++) {
                uint32_t a0[4];
                ldsm4(a0, su + (uint32_t)((wm + l15) * ST_WSK + l * 64 + kb * 16 + lc8) * 2);
                uint32_t bf0[4], bf1[4];
                uint32_t bAddr = su + (uint32_t)(abuf + (kb * 16 + l15) * ST_X + wn + lc8) * 2;
                ldsm4t(bf0, bAddr);
                ldsm4t(bf1, bAddr + 32);
                mma16816(acc[0], a0, &bf0[0]);
                mma16816(acc[1], a0, &bf0[2]);
                mma16816(acc[2], a0, &bf1[0]);
                mma16816(acc[3], a0, &bf1[2]);
            }
            nstage++;
        }
        // write relu(skip_sum + bsum) into sS
        {
            int o_a = wm + g, o_b = wm + 8 + g;
            float ba = g_bsum[o_a], bb = g_bsum[o_b];
#pragma unroll
            for (int nt = 0; nt < 4; nt++) {
                int j0 = wn + nt * 8 + 2 * tig;
                sS[o_a * 132 + j0]     = fmaxf(acc[nt][0] + ba, 0.f);
                sS[o_a * 132 + j0 + 1] = fmaxf(acc[nt][1] + ba, 0.f);
                sS[o_b * 132 + j0]     = fmaxf(acc[nt][2] + bb, 0.f);
                sS[o_b * 132 + j0 + 1] = fmaxf(acc[nt][3] + bb, 0.f);
            }
        }
        __syncthreads();

        // fp32 scalar head: relu(ow1 . s + ob1), then ow2 . u + ob2
        {
            int tl = tid >> 2, pq = tid & 3;      // 128 timesteps x 4-thread quads
            float a2[16];
#pragma unroll
            for (int q = 0; q < 16; q++) a2[q] = sb1[4 * q + pq];
#pragma unroll 4
            for (int cch = 0; cch < 64; cch++) {
                float v = sS[cch * 132 + tl];    // already relu'd
#pragma unroll
                for (int q = 0; q < 16; q++) a2[q] = fmaf(sW1o[cch * 68 + 4 * q + pq], v, a2[q]);
            }
            float y = 0.f;
#pragma unroll
            for (int q = 0; q < 16; q++) y += sw2[4 * q + pq] * fmaxf(a2[q], 0.f);
            y += __shfl_xor_sync(0xFFFFFFFFu, y, 1);
            y += __shfl_xor_sync(0xFFFFFFFFu, y, 2);
            if (pq == 0) out[b * Tt + t0 + tl] = y + ob2[0];
        }
        __syncthreads();
    }
}

// ---------------- launcher ----------------
extern "C" void kernel_launch(void* const* d_in, const int* in_sizes, int n_in,
                              void* d_out, int out_size) {
    (void)in_sizes; (void)n_in; (void)out_size;
    const float* x    = (const float*)d_in[0];
    const float* w_in = (const float*)d_in[1];
    const float* b_in = (const float*)d_in[2];
    const float* fw   = (const float*)d_in[3];
    const float* fb   = (const float*)d_in[4];
    const float* gw   = (const float*)d_in[5];
    const float* gb   = (const float*)d_in[6];
    const float* rw   = (const float*)d_in[7];
    const float* rb   = (const float*)d_in[8];
    const float* sw   = (const float*)d_in[9];
    const float* sb   = (const float*)d_in[10];
    const float* ow1  = (const float*)d_in[11];
    const float* ob1  = (const float*)d_in[12];
    const float* ow2  = (const float*)d_in[13];
    const float* ob2  = (const float*)d_in[14];
    float* out = (float*)d_out;

    static const int dil[Ll] = {1, 2, 4, 8, 16, 32, 64, 128, 256, 512};

    cudaFuncSetAttribute((const void*)layer_kernel,
                         cudaFuncAttributeMaxDynamicSharedMemorySize, L_SMEM_BYTES);
    cudaFuncSetAttribute((const void*)output_kernel,
                         cudaFuncAttributeMaxDynamicSharedMemorySize, O_SMEM_BYTES);

    prep_kernel<<<960, 256>>>(fw, fb, gw, gb, rw, rb, sw, sb);
    input_conv_kernel<<<(Bb * Tt) / 128, 256>>>(x, w_in, b_in);

    int buf = 0;
    for (int l = 0; l < Ll; l++) {
        layer_kernel<<<GRIDP, 512, L_SMEM_BYTES>>>(l, dil[l], buf);
        buf ^= 1;
    }
    output_kernel<<<GRIDP, 512, O_SMEM_BYTES>>>(ow1, ob1, ow2, ob2, out);
}